// round 4
// baseline (speedup 1.0000x reference)
#include <cuda_runtime.h>
#include <cuda_bf16.h>

// ---------------------------------------------------------------------------
// 18-qubit statevector fidelity |<psi2|psi1>|^2, hardware-efficient ansatz.
// R4: packed f32x2 complex arithmetic (FFMA2) — each amplitude lives in one
// 64-bit register pair (re,im). Gate = 1 mul.rn.f32x2 + 3 fma.rn.f32x2 per
// output amp (2x fewer FMA-pipe ops vs scalar). Structure as R3:
//   passA: q0,q1(reg) q2-6(shfl) | smem transpose | q7,q8(reg) q9(shfl)
//   passB: q10-14(shfl)          | smem transpose | q15,16(reg) q17(shfl) + CZ
// 4 amps/thread, 512 blocks x 256 threads per pass.
// ---------------------------------------------------------------------------

#define NQ 18
#define NL 6
#define NSTATE (1 << NQ)

typedef unsigned long long u64;

__device__ float2 d_psi[2][NSTATE];
// Packed duplicated gate coefficients: per (s,l,q):
// [0]=P00 [1]=Q00 [2]=P01 [3]=Q01 [4]=P10 [5]=Q10 [6]=P11 [7]=Q11
// where P(m)=(m.x,m.x), Q(m)=(-m.y,m.y)
__device__ u64 d_matsP[2][NL][NQ][8];
__device__ double d_acc[2];

// ---- packed helpers -------------------------------------------------------
__device__ __forceinline__ u64 f2pack(float lo, float hi) {
    u64 r;
    asm("mov.b64 %0, {%1, %2};" : "=l"(r) : "f"(lo), "f"(hi));
    return r;
}
__device__ __forceinline__ void f2unpack(u64 a, float& lo, float& hi) {
    asm("mov.b64 {%0, %1}, %2;" : "=f"(lo), "=f"(hi) : "l"(a));
}
__device__ __forceinline__ u64 fma2(u64 a, u64 b, u64 c) {
    u64 d;
    asm("fma.rn.f32x2 %0, %1, %2, %3;" : "=l"(d) : "l"(a), "l"(b), "l"(c));
    return d;
}
__device__ __forceinline__ u64 mul2(u64 a, u64 b) {
    u64 d;
    asm("mul.rn.f32x2 %0, %1, %2;" : "=l"(d) : "l"(a), "l"(b));
    return d;
}

__device__ __forceinline__ float2 cmulh(float2 a, float2 b) {
    return make_float2(a.x * b.x - a.y * b.y, a.x * b.y + a.y * b.x);
}
__device__ __forceinline__ float2 caddh(float2 a, float2 b) {
    return make_float2(a.x + b.x, a.y + b.y);
}
__device__ __forceinline__ float2 rscaleh(float r, float2 v) {
    return make_float2(r * v.x, r * v.y);
}

// ---------------------------------------------------------------------------
// Prep: fused M = RZ*RY*RX per (state,layer,qubit), stored packed-duplicated.
// ---------------------------------------------------------------------------
__global__ void qk_prep(const float* __restrict__ x1, const float* __restrict__ x2,
                        const float* __restrict__ iscale, const float* __restrict__ var) {
    int t = threadIdx.x;
    if (t < 2) d_acc[t] = 0.0;
    if (t >= 2 * NL * NQ) return;
    int s = t / (NL * NQ);
    int r = t % (NL * NQ);
    int l = r / NQ;
    int q = r % NQ;
    const float* x = s ? x2 : x1;

    float a = iscale[l * NQ + q] * x[q];
    float b = var[l * 2 * NQ + q];
    float c = var[l * 2 * NQ + NQ + q];

    float sa, ca, sb, cb, sc, cc;
    sincosf(0.5f * a, &sa, &ca);
    sincosf(0.5f * b, &sb, &cb);
    sincosf(0.5f * c, &sc, &cc);

    float2 X00 = make_float2(ca, 0.f), X01 = make_float2(0.f, -sa);
    float2 X10 = make_float2(0.f, -sa), X11 = make_float2(ca, 0.f);
    float2 M100 = caddh(rscaleh(cb, X00), rscaleh(-sb, X10));
    float2 M101 = caddh(rscaleh(cb, X01), rscaleh(-sb, X11));
    float2 M110 = caddh(rscaleh(sb, X00), rscaleh(cb, X10));
    float2 M111 = caddh(rscaleh(sb, X01), rscaleh(cb, X11));
    float2 e0 = make_float2(cc, -sc);
    float2 e1 = make_float2(cc, sc);
    float2 m00 = cmulh(e0, M100);
    float2 m01 = cmulh(e0, M101);
    float2 m10 = cmulh(e1, M110);
    float2 m11 = cmulh(e1, M111);

    u64* g = d_matsP[s][l][q];
    g[0] = f2pack(m00.x, m00.x);
    g[1] = f2pack(-m00.y, m00.y);
    g[2] = f2pack(m01.x, m01.x);
    g[3] = f2pack(-m01.y, m01.y);
    g[4] = f2pack(m10.x, m10.x);
    g[5] = f2pack(-m10.y, m10.y);
    g[6] = f2pack(m11.x, m11.x);
    g[7] = f2pack(-m11.y, m11.y);
}

// gate on register pair: a' = m00*a + m01*b ; b' = m10*a + m11*b
__device__ __forceinline__ void gate_pairP(u64& a, u64& b, const u64* g) {
    float alo, ahi, blo, bhi;
    f2unpack(a, alo, ahi);
    f2unpack(b, blo, bhi);
    u64 sa = f2pack(ahi, alo);
    u64 sb = f2pack(bhi, blo);
    u64 na = fma2(g[2], b, fma2(g[3], sb, fma2(g[1], sa, mul2(g[0], a))));
    u64 nb = fma2(g[6], b, fma2(g[7], sb, fma2(g[5], sa, mul2(g[4], a))));
    a = na;
    b = nb;
}

// gate along a lane bit: r = ca*v + cb*p, p = partner amp (shfl)
__device__ __forceinline__ u64 gate_shflP(u64 v, int mask, u64 Pca, u64 Qca, u64 Pcb, u64 Qcb) {
    float lo, hi;
    f2unpack(v, lo, hi);
    float plo = __shfl_xor_sync(0xFFFFFFFFu, lo, mask);
    float phi = __shfl_xor_sync(0xFFFFFFFFu, hi, mask);
    u64 sv = f2pack(hi, lo);
    u64 p = f2pack(plo, phi);
    u64 sp = f2pack(phi, plo);
    return fma2(Pcb, p, fma2(Qcb, sp, fma2(Qca, sv, mul2(Pca, v))));
}

// smem swizzle over 10-bit local index: conflict-free for both transpose patterns
__device__ __forceinline__ unsigned swz(unsigned l) {
    return l ^ ((l >> 4) & 3u) ^ ((l >> 8) & 2u);
}

#define SHFL_GATE(Gq, mask)                                                   \
    {                                                                         \
        const u64* gq = (Gq);                                                 \
        bool hi = (lane & (mask)) != 0;                                       \
        u64 Pca = hi ? gq[6] : gq[0];                                         \
        u64 Qca = hi ? gq[7] : gq[1];                                         \
        u64 Pcb = hi ? gq[4] : gq[2];                                         \
        u64 Qcb = hi ? gq[5] : gq[3];                                         \
        _Pragma("unroll") for (int k = 0; k < 4; k++)                         \
            v[k] = gate_shflP(v[k], (mask), Pca, Qca, Pcb, Qcb);              \
    }

// ---------------------------------------------------------------------------
// passA: qubits 0..9. Local 10-bit index == global bits 0-9, blk -> bits 10-17.
// mapping1: l = k | lane<<2 | w<<7
// mapping2: l = (w&3) | (w>>2)<<6 | (lane&1)<<9 | ((lane>>1)&15)<<2 | k<<7
// ---------------------------------------------------------------------------
__global__ void __launch_bounds__(256) qk_passA(int layer, int init) {
    __shared__ u64 sm[1024];
    int tid = threadIdx.x;
    int lane = tid & 31;
    int w = tid >> 5;
    int blk = blockIdx.x;
    int s = blk >> 8;
    unsigned blkbase = ((unsigned)(blk & 255)) << 10;
    u64* psi = (u64*)d_psi[s];
    const u64* G = &d_matsP[s][layer][0][0];

    unsigned l1 = ((unsigned)lane << 2) | ((unsigned)w << 7);
    u64 v[4];

    if (init) {
        v[0] = v[1] = v[2] = v[3] = 0ull;
        if ((blkbase | l1) == 0) v[0] = f2pack(1.f, 0.f);
    } else {
        const ulonglong2* p2 = (const ulonglong2*)(psi + blkbase + l1);
        ulonglong2 a = p2[0], b = p2[1];
        v[0] = a.x; v[1] = a.y; v[2] = b.x; v[3] = b.y;
    }

    // reg gates q0 (stride 1), q1 (stride 2)
    gate_pairP(v[0], v[1], G + 0);
    gate_pairP(v[2], v[3], G + 0);
    gate_pairP(v[0], v[2], G + 8);
    gate_pairP(v[1], v[3], G + 8);

    // shfl gates q2..q6 (lane bits 0..4)
    SHFL_GATE(G + 16, 1)
    SHFL_GATE(G + 24, 2)
    SHFL_GATE(G + 32, 4)
    SHFL_GATE(G + 40, 8)
    SHFL_GATE(G + 48, 16)

    // transpose
#pragma unroll
    for (int k = 0; k < 4; k++) sm[swz(l1 | k)] = v[k];
    __syncthreads();

    unsigned base2 = (unsigned)(w & 3) | ((unsigned)(w >> 2) << 6)
                   | ((unsigned)(lane & 1) << 9) | ((unsigned)((lane >> 1) & 15) << 2);
#pragma unroll
    for (int k = 0; k < 4; k++) v[k] = sm[swz(base2 | ((unsigned)k << 7))];

    // reg gates q7 (k stride 1), q8 (k stride 2)
    gate_pairP(v[0], v[1], G + 56);
    gate_pairP(v[2], v[3], G + 56);
    gate_pairP(v[0], v[2], G + 64);
    gate_pairP(v[1], v[3], G + 64);

    // shfl gate q9 (lane bit 0)
    SHFL_GATE(G + 72, 1)

#pragma unroll
    for (int k = 0; k < 4; k++)
        psi[blkbase + base2 + ((unsigned)k << 7)] = v[k];
}

// ---------------------------------------------------------------------------
// passB: qubits 10..17 + CZ sign. Block owns global bits {0,1,10..17};
// global(l) = (l&3) | rest<<2 | (l>>2)<<10, rest = blockIdx bits -> global 2-9.
// ---------------------------------------------------------------------------
__global__ void __launch_bounds__(256) qk_passB(int layer) {
    __shared__ u64 sm[1024];
    int tid = threadIdx.x;
    int lane = tid & 31;
    int w = tid >> 5;
    int blk = blockIdx.x;
    int s = blk >> 8;
    unsigned rest = (unsigned)(blk & 255);
    u64* psi = (u64*)d_psi[s];
    const u64* G = &d_matsP[s][layer][0][0];

    unsigned l1 = ((unsigned)lane << 2) | ((unsigned)w << 7);
    unsigned g1 = (l1 & 3u) | (rest << 2) | ((l1 >> 2) << 10);

    u64 v[4];
    {
        const ulonglong2* p2 = (const ulonglong2*)(psi + g1);
        ulonglong2 a = p2[0], b = p2[1];
        v[0] = a.x; v[1] = a.y; v[2] = b.x; v[3] = b.y;
    }

    // shfl gates q10..q14 (lane bits 0..4)
    SHFL_GATE(G + 80, 1)
    SHFL_GATE(G + 88, 2)
    SHFL_GATE(G + 96, 4)
    SHFL_GATE(G + 104, 8)
    SHFL_GATE(G + 112, 16)

#pragma unroll
    for (int k = 0; k < 4; k++) sm[swz(l1 | k)] = v[k];
    __syncthreads();

    unsigned base2 = (unsigned)(w & 3) | ((unsigned)(w >> 2) << 6)
                   | ((unsigned)(lane & 1) << 9) | ((unsigned)((lane >> 1) & 15) << 2);
#pragma unroll
    for (int k = 0; k < 4; k++) v[k] = sm[swz(base2 | ((unsigned)k << 7))];

    // reg gates q15 (k stride 1), q16 (k stride 2)
    gate_pairP(v[0], v[1], G + 120);
    gate_pairP(v[2], v[3], G + 120);
    gate_pairP(v[0], v[2], G + 128);
    gate_pairP(v[1], v[3], G + 128);

    // shfl gate q17 (lane bit 0 of mapping2)
    SHFL_GATE(G + 136, 1)

    // CZ chain sign + store
#pragma unroll
    for (int k = 0; k < 4; k++) {
        unsigned l2 = base2 | ((unsigned)k << 7);
        unsigned g = (l2 & 3u) | (rest << 2) | ((l2 >> 2) << 10);
        unsigned tm = g & (g >> 1) & 0x1FFFFu;
        if (__popc(tm) & 1) v[k] ^= 0x8000000080000000ull;
        psi[g] = v[k];
    }
}

// ---------------------------------------------------------------------------
// Overlap reduction: acc += conj(psi2) . psi1
// ---------------------------------------------------------------------------
__global__ void qk_reduce() {
    int t = blockIdx.x * blockDim.x + threadIdx.x;
    int nthreads = gridDim.x * blockDim.x;
    double re = 0.0, im = 0.0;
    for (int i = t; i < NSTATE; i += nthreads) {
        float2 a = d_psi[0][i];
        float2 b = d_psi[1][i];
        re += (double)b.x * a.x + (double)b.y * a.y;
        im += (double)b.x * a.y - (double)b.y * a.x;
    }
#pragma unroll
    for (int o = 16; o > 0; o >>= 1) {
        re += __shfl_down_sync(0xFFFFFFFFu, re, o);
        im += __shfl_down_sync(0xFFFFFFFFu, im, o);
    }
    if ((threadIdx.x & 31) == 0) {
        atomicAdd(&d_acc[0], re);
        atomicAdd(&d_acc[1], im);
    }
}

__global__ void qk_final(float* out) {
    double re = d_acc[0], im = d_acc[1];
    out[0] = (float)(re * re + im * im);
}

extern "C" void kernel_launch(void* const* d_in, const int* in_sizes, int n_in,
                              void* d_out, int out_size) {
    const float* x1 = (const float*)d_in[0];
    const float* x2 = (const float*)d_in[1];
    const float* iscale = (const float*)d_in[2];
    const float* var = (const float*)d_in[3];

    qk_prep<<<1, 256>>>(x1, x2, iscale, var);
    for (int l = 0; l < NL; l++) {
        qk_passA<<<512, 256>>>(l, l == 0 ? 1 : 0);
        qk_passB<<<512, 256>>>(l);
    }
    qk_reduce<<<148, 256>>>();
    qk_final<<<1, 1>>>((float*)d_out);
}

// round 5
// speedup vs baseline: 1.2498x; 1.2498x over previous
#include <cuda_runtime.h>
#include <cuda_bf16.h>

// ---------------------------------------------------------------------------
// 18-qubit statevector fidelity |<psi2|psi1>|^2, hardware-efficient ansatz.
// R5: R3 structure (4 amps/thread, 512x256 per pass, XOR-swizzled smem
// transpose) + explicit fmaf gate chains (minimal FMA count, neg folded into
// FFMA modifiers) + gate matrices staged in smem (broadcast LDS, no repeated
// global coefficient loads).
//   passA: q0,q1(reg) q2-6(shfl) | transpose | q7,q8(reg) q9(shfl)
//   passB: q10-14(shfl)          | transpose | q15,16(reg) q17(shfl) + CZ
// ---------------------------------------------------------------------------

#define NQ 18
#define NL 6
#define NSTATE (1 << NQ)

__device__ float2 d_psi[2][NSTATE];
// per (s,l,q): f4[0] = (m00.x, m00.y, m01.x, m01.y), f4[1] = (m10.x, m10.y, m11.x, m11.y)
__device__ float4 d_mats[2][NL][NQ][2];
__device__ double d_acc[2];

__device__ __forceinline__ float2 cmulh(float2 a, float2 b) {
    return make_float2(a.x * b.x - a.y * b.y, a.x * b.y + a.y * b.x);
}
__device__ __forceinline__ float2 caddh(float2 a, float2 b) {
    return make_float2(a.x + b.x, a.y + b.y);
}
__device__ __forceinline__ float2 rscaleh(float r, float2 v) {
    return make_float2(r * v.x, r * v.y);
}

__global__ void qk_prep(const float* __restrict__ x1, const float* __restrict__ x2,
                        const float* __restrict__ iscale, const float* __restrict__ var) {
    int t = threadIdx.x;
    if (t < 2) d_acc[t] = 0.0;
    if (t >= 2 * NL * NQ) return;
    int s = t / (NL * NQ);
    int r = t % (NL * NQ);
    int l = r / NQ;
    int q = r % NQ;
    const float* x = s ? x2 : x1;

    float a = iscale[l * NQ + q] * x[q];
    float b = var[l * 2 * NQ + q];
    float c = var[l * 2 * NQ + NQ + q];

    float sa, ca, sb, cb, sc, cc;
    sincosf(0.5f * a, &sa, &ca);
    sincosf(0.5f * b, &sb, &cb);
    sincosf(0.5f * c, &sc, &cc);

    float2 X00 = make_float2(ca, 0.f), X01 = make_float2(0.f, -sa);
    float2 X10 = make_float2(0.f, -sa), X11 = make_float2(ca, 0.f);
    float2 M100 = caddh(rscaleh(cb, X00), rscaleh(-sb, X10));
    float2 M101 = caddh(rscaleh(cb, X01), rscaleh(-sb, X11));
    float2 M110 = caddh(rscaleh(sb, X00), rscaleh(cb, X10));
    float2 M111 = caddh(rscaleh(sb, X01), rscaleh(cb, X11));
    float2 e0 = make_float2(cc, -sc);
    float2 e1 = make_float2(cc, sc);
    float2 m00 = cmulh(e0, M100);
    float2 m01 = cmulh(e0, M101);
    float2 m10 = cmulh(e1, M110);
    float2 m11 = cmulh(e1, M111);

    d_mats[s][l][q][0] = make_float4(m00.x, m00.y, m01.x, m01.y);
    d_mats[s][l][q][1] = make_float4(m10.x, m10.y, m11.x, m11.y);
}

// gate on register pair: a' = m00*a + m01*b ; b' = m10*a + m11*b
// c0 = (m00.x, m00.y, m01.x, m01.y), c1 = (m10.x, m10.y, m11.x, m11.y)
__device__ __forceinline__ void gate_pair(float2& a, float2& b, float4 c0, float4 c1) {
    float nax = fmaf(c0.z, b.x, fmaf(-c0.w, b.y, fmaf(c0.x, a.x, -c0.y * a.y)));
    float nay = fmaf(c0.z, b.y, fmaf(c0.w, b.x, fmaf(c0.x, a.y, c0.y * a.x)));
    float nbx = fmaf(c1.z, b.x, fmaf(-c1.w, b.y, fmaf(c1.x, a.x, -c1.y * a.y)));
    float nby = fmaf(c1.z, b.y, fmaf(c1.w, b.x, fmaf(c1.x, a.y, c1.y * a.x)));
    a = make_float2(nax, nay);
    b = make_float2(nbx, nby);
}

// gate along a lane bit: r = ca*v + cb*p, coefficients pre-selected per lane
__device__ __forceinline__ float2 gate_shfl(float2 v, int mask,
                                            float cax, float cay, float cbx, float cby) {
    float px = __shfl_xor_sync(0xFFFFFFFFu, v.x, mask);
    float py = __shfl_xor_sync(0xFFFFFFFFu, v.y, mask);
    float rx = fmaf(cbx, px, fmaf(-cby, py, fmaf(cax, v.x, -cay * v.y)));
    float ry = fmaf(cbx, py, fmaf(cby, px, fmaf(cax, v.y, cay * v.x)));
    return make_float2(rx, ry);
}

// smem swizzle over 10-bit local index: conflict-free for both transpose patterns
__device__ __forceinline__ unsigned swz(unsigned l) {
    return l ^ ((l >> 4) & 3u) ^ ((l >> 8) & 2u);
}

// per-qubit shfl gate with lane-hoisted coefficient selection; j = smem mat index
#define SHFL_GATE(j, mask)                                                    \
    {                                                                         \
        float4 c0 = sMat[2 * (j)], c1 = sMat[2 * (j) + 1];                    \
        bool hi = (lane & (mask)) != 0;                                       \
        float cax = hi ? c1.z : c0.x;                                         \
        float cay = hi ? c1.w : c0.y;                                         \
        float cbx = hi ? c1.x : c0.z;                                         \
        float cby = hi ? c1.y : c0.w;                                         \
        _Pragma("unroll") for (int k = 0; k < 4; k++)                         \
            v[k] = gate_shfl(v[k], (mask), cax, cay, cbx, cby);               \
    }

// ---------------------------------------------------------------------------
// passA: qubits 0..9. Local 10-bit index == global bits 0-9, blk -> bits 10-17.
// mapping1: l = k | lane<<2 | w<<7
// mapping2: l = (w&3) | (w>>2)<<6 | (lane&1)<<9 | ((lane>>1)&15)<<2 | k<<7
// ---------------------------------------------------------------------------
__global__ void __launch_bounds__(256) qk_passA(int layer, int init) {
    __shared__ float2 sm[1024];
    __shared__ float4 sMat[20];
    int tid = threadIdx.x;
    int lane = tid & 31;
    int w = tid >> 5;
    int blk = blockIdx.x;
    int s = blk >> 8;
    unsigned blkbase = ((unsigned)(blk & 255)) << 10;
    float2* psi = d_psi[s];

    if (tid < 20) sMat[tid] = (&d_mats[s][layer][0][0])[tid];

    unsigned l1 = ((unsigned)lane << 2) | ((unsigned)w << 7);
    float2 v[4];

    if (init) {
#pragma unroll
        for (int k = 0; k < 4; k++) v[k] = make_float2(0.f, 0.f);
        if ((blkbase | l1) == 0) v[0] = make_float2(1.f, 0.f);
    } else {
        const float4* p4 = (const float4*)(psi + blkbase + l1);
        float4 a = p4[0], b = p4[1];
        v[0] = make_float2(a.x, a.y);
        v[1] = make_float2(a.z, a.w);
        v[2] = make_float2(b.x, b.y);
        v[3] = make_float2(b.z, b.w);
    }
    __syncthreads();

    // reg gates q0 (stride 1), q1 (stride 2)
    {
        float4 c0 = sMat[0], c1 = sMat[1];
        gate_pair(v[0], v[1], c0, c1);
        gate_pair(v[2], v[3], c0, c1);
    }
    {
        float4 c0 = sMat[2], c1 = sMat[3];
        gate_pair(v[0], v[2], c0, c1);
        gate_pair(v[1], v[3], c0, c1);
    }
    // shfl gates q2..q6 (lane bits 0..4)
    SHFL_GATE(2, 1)
    SHFL_GATE(3, 2)
    SHFL_GATE(4, 4)
    SHFL_GATE(5, 8)
    SHFL_GATE(6, 16)

    // transpose
    unsigned sb1 = swz(l1);
#pragma unroll
    for (int k = 0; k < 4; k++) sm[sb1 ^ (unsigned)k] = v[k];
    __syncthreads();

    unsigned base2 = (unsigned)(w & 3) | ((unsigned)(w >> 2) << 6)
                   | ((unsigned)(lane & 1) << 9) | ((unsigned)((lane >> 1) & 15) << 2);
    unsigned sb2 = swz(base2);
#pragma unroll
    for (int k = 0; k < 4; k++) v[k] = sm[sb2 + ((unsigned)k << 7)];

    // reg gates q7 (k stride 1), q8 (k stride 2)
    {
        float4 c0 = sMat[14], c1 = sMat[15];
        gate_pair(v[0], v[1], c0, c1);
        gate_pair(v[2], v[3], c0, c1);
    }
    {
        float4 c0 = sMat[16], c1 = sMat[17];
        gate_pair(v[0], v[2], c0, c1);
        gate_pair(v[1], v[3], c0, c1);
    }
    // shfl gate q9 (lane bit 0)
    SHFL_GATE(9, 1)

#pragma unroll
    for (int k = 0; k < 4; k++)
        psi[blkbase + base2 + ((unsigned)k << 7)] = v[k];
}

// ---------------------------------------------------------------------------
// passB: qubits 10..17 + CZ sign. Block owns global bits {0,1,10..17};
// global(l) = (l&3) | rest<<2 | (l>>2)<<10, rest = blockIdx bits -> global 2-9.
// ---------------------------------------------------------------------------
__global__ void __launch_bounds__(256) qk_passB(int layer) {
    __shared__ float2 sm[1024];
    __shared__ float4 sMat[16];
    int tid = threadIdx.x;
    int lane = tid & 31;
    int w = tid >> 5;
    int blk = blockIdx.x;
    int s = blk >> 8;
    unsigned rest = (unsigned)(blk & 255);
    float2* psi = d_psi[s];

    if (tid < 16) sMat[tid] = (&d_mats[s][layer][10][0])[tid];

    unsigned l1 = ((unsigned)lane << 2) | ((unsigned)w << 7);
    unsigned g1 = (l1 & 3u) | (rest << 2) | ((l1 >> 2) << 10);

    float2 v[4];
    {
        const float4* p4 = (const float4*)(psi + g1);
        float4 a = p4[0], b = p4[1];
        v[0] = make_float2(a.x, a.y);
        v[1] = make_float2(a.z, a.w);
        v[2] = make_float2(b.x, b.y);
        v[3] = make_float2(b.z, b.w);
    }
    __syncthreads();

    // shfl gates q10..q14 (lane bits 0..4); smem mat index j = q-10
    SHFL_GATE(0, 1)
    SHFL_GATE(1, 2)
    SHFL_GATE(2, 4)
    SHFL_GATE(3, 8)
    SHFL_GATE(4, 16)

    unsigned sb1 = swz(l1);
#pragma unroll
    for (int k = 0; k < 4; k++) sm[sb1 ^ (unsigned)k] = v[k];
    __syncthreads();

    unsigned base2 = (unsigned)(w & 3) | ((unsigned)(w >> 2) << 6)
                   | ((unsigned)(lane & 1) << 9) | ((unsigned)((lane >> 1) & 15) << 2);
    unsigned sb2 = swz(base2);
#pragma unroll
    for (int k = 0; k < 4; k++) v[k] = sm[sb2 + ((unsigned)k << 7)];

    // reg gates q15 (k stride 1), q16 (k stride 2)
    {
        float4 c0 = sMat[10], c1 = sMat[11];
        gate_pair(v[0], v[1], c0, c1);
        gate_pair(v[2], v[3], c0, c1);
    }
    {
        float4 c0 = sMat[12], c1 = sMat[13];
        gate_pair(v[0], v[2], c0, c1);
        gate_pair(v[1], v[3], c0, c1);
    }
    // shfl gate q17 (lane bit 0 of mapping2)
    SHFL_GATE(7, 1)

    // CZ chain sign + store
#pragma unroll
    for (int k = 0; k < 4; k++) {
        unsigned l2 = base2 | ((unsigned)k << 7);
        unsigned g = (l2 & 3u) | (rest << 2) | ((l2 >> 2) << 10);
        unsigned tm = g & (g >> 1) & 0x1FFFFu;
        if (__popc(tm) & 1) {
            v[k].x = -v[k].x;
            v[k].y = -v[k].y;
        }
        psi[g] = v[k];
    }
}

__global__ void qk_reduce() {
    int t = blockIdx.x * blockDim.x + threadIdx.x;
    int nthreads = gridDim.x * blockDim.x;
    double re = 0.0, im = 0.0;
    for (int i = t; i < NSTATE; i += nthreads) {
        float2 a = d_psi[0][i];
        float2 b = d_psi[1][i];
        re += (double)b.x * a.x + (double)b.y * a.y;
        im += (double)b.x * a.y - (double)b.y * a.x;
    }
#pragma unroll
    for (int o = 16; o > 0; o >>= 1) {
        re += __shfl_down_sync(0xFFFFFFFFu, re, o);
        im += __shfl_down_sync(0xFFFFFFFFu, im, o);
    }
    if ((threadIdx.x & 31) == 0) {
        atomicAdd(&d_acc[0], re);
        atomicAdd(&d_acc[1], im);
    }
}

__global__ void qk_final(float* out) {
    double re = d_acc[0], im = d_acc[1];
    out[0] = (float)(re * re + im * im);
}

extern "C" void kernel_launch(void* const* d_in, const int* in_sizes, int n_in,
                              void* d_out, int out_size) {
    const float* x1 = (const float*)d_in[0];
    const float* x2 = (const float*)d_in[1];
    const float* iscale = (const float*)d_in[2];
    const float* var = (const float*)d_in[3];

    qk_prep<<<1, 256>>>(x1, x2, iscale, var);
    for (int l = 0; l < NL; l++) {
        qk_passA<<<512, 256>>>(l, l == 0 ? 1 : 0);
        qk_passB<<<512, 256>>>(l);
    }
    qk_reduce<<<148, 256>>>();
    qk_final<<<1, 1>>>((float*)d_out);
}

// round 6
// speedup vs baseline: 1.2706x; 1.0166x over previous
#include <cuda_runtime.h>
#include <cuda_bf16.h>

// ---------------------------------------------------------------------------
// 18-qubit statevector fidelity |<psi2|psi1>|^2, hardware-efficient ansatz.
// R6: 2 amps/thread (256K threads, 8192 warps ~ 14/SMSP) for latency hiding.
// 512-thread blocks, 10-bit amp window, one XOR-swizzled smem transpose/pass.
//   passA: q0(reg) q1-5(shfl) | transpose | q6(reg) q7-9(shfl)
//   passB: q10-13(shfl)       | transpose | q14(reg) q15-17(shfl) + CZ
// Gate matrices staged in smem; explicit fmaf chains (8 FMA-ops/amp/gate).
// ---------------------------------------------------------------------------

#define NQ 18
#define NL 6
#define NSTATE (1 << NQ)

__device__ float2 d_psi[2][NSTATE];
// per (s,l,q): f4[0] = (m00.x, m00.y, m01.x, m01.y), f4[1] = (m10.x, m10.y, m11.x, m11.y)
__device__ float4 d_mats[2][NL][NQ][2];
__device__ double d_acc[2];

__device__ __forceinline__ float2 cmulh(float2 a, float2 b) {
    return make_float2(a.x * b.x - a.y * b.y, a.x * b.y + a.y * b.x);
}
__device__ __forceinline__ float2 caddh(float2 a, float2 b) {
    return make_float2(a.x + b.x, a.y + b.y);
}
__device__ __forceinline__ float2 rscaleh(float r, float2 v) {
    return make_float2(r * v.x, r * v.y);
}

__global__ void qk_prep(const float* __restrict__ x1, const float* __restrict__ x2,
                        const float* __restrict__ iscale, const float* __restrict__ var) {
    int t = threadIdx.x;
    if (t < 2) d_acc[t] = 0.0;
    if (t >= 2 * NL * NQ) return;
    int s = t / (NL * NQ);
    int r = t % (NL * NQ);
    int l = r / NQ;
    int q = r % NQ;
    const float* x = s ? x2 : x1;

    float a = iscale[l * NQ + q] * x[q];
    float b = var[l * 2 * NQ + q];
    float c = var[l * 2 * NQ + NQ + q];

    float sa, ca, sb, cb, sc, cc;
    sincosf(0.5f * a, &sa, &ca);
    sincosf(0.5f * b, &sb, &cb);
    sincosf(0.5f * c, &sc, &cc);

    float2 X00 = make_float2(ca, 0.f), X01 = make_float2(0.f, -sa);
    float2 X10 = make_float2(0.f, -sa), X11 = make_float2(ca, 0.f);
    float2 M100 = caddh(rscaleh(cb, X00), rscaleh(-sb, X10));
    float2 M101 = caddh(rscaleh(cb, X01), rscaleh(-sb, X11));
    float2 M110 = caddh(rscaleh(sb, X00), rscaleh(cb, X10));
    float2 M111 = caddh(rscaleh(sb, X01), rscaleh(cb, X11));
    float2 e0 = make_float2(cc, -sc);
    float2 e1 = make_float2(cc, sc);
    float2 m00 = cmulh(e0, M100);
    float2 m01 = cmulh(e0, M101);
    float2 m10 = cmulh(e1, M110);
    float2 m11 = cmulh(e1, M111);

    d_mats[s][l][q][0] = make_float4(m00.x, m00.y, m01.x, m01.y);
    d_mats[s][l][q][1] = make_float4(m10.x, m10.y, m11.x, m11.y);
}

// gate on register pair: a' = m00*a + m01*b ; b' = m10*a + m11*b
__device__ __forceinline__ void gate_pair(float2& a, float2& b, float4 c0, float4 c1) {
    float nax = fmaf(c0.z, b.x, fmaf(-c0.w, b.y, fmaf(c0.x, a.x, -c0.y * a.y)));
    float nay = fmaf(c0.z, b.y, fmaf(c0.w, b.x, fmaf(c0.x, a.y, c0.y * a.x)));
    float nbx = fmaf(c1.z, b.x, fmaf(-c1.w, b.y, fmaf(c1.x, a.x, -c1.y * a.y)));
    float nby = fmaf(c1.z, b.y, fmaf(c1.w, b.x, fmaf(c1.x, a.y, c1.y * a.x)));
    a = make_float2(nax, nay);
    b = make_float2(nbx, nby);
}

// gate along a lane bit: r = ca*v + cb*p (coefficients pre-selected per lane)
__device__ __forceinline__ float2 gate_shfl(float2 v, int mask,
                                            float cax, float cay, float cbx, float cby) {
    float px = __shfl_xor_sync(0xFFFFFFFFu, v.x, mask);
    float py = __shfl_xor_sync(0xFFFFFFFFu, v.y, mask);
    float rx = fmaf(cbx, px, fmaf(-cby, py, fmaf(cax, v.x, -cay * v.y)));
    float ry = fmaf(cbx, py, fmaf(cby, px, fmaf(cax, v.y, cay * v.x)));
    return make_float2(rx, ry);
}

// smem swizzle over 10-bit local index: conflict-free for STS (bits 1-5 vary)
// and LDS (bits {7,8,9,0,1} vary) half-warp phases.
__device__ __forceinline__ unsigned swz(unsigned a) {
    return a ^ ((a >> 4) & 15u) ^ ((a >> 7) & 6u);
}

// shfl gate for both amps; j = smem mat pair index
#define SHFL_GATE(j, mask)                                                    \
    {                                                                         \
        float4 c0 = sMat[2 * (j)], c1 = sMat[2 * (j) + 1];                    \
        bool hi = (lane & (mask)) != 0;                                       \
        float cax = hi ? c1.z : c0.x;                                         \
        float cay = hi ? c1.w : c0.y;                                         \
        float cbx = hi ? c1.x : c0.z;                                         \
        float cby = hi ? c1.y : c0.w;                                         \
        v[0] = gate_shfl(v[0], (mask), cax, cay, cbx, cby);                   \
        v[1] = gate_shfl(v[1], (mask), cax, cay, cbx, cby);                   \
    }

// ---------------------------------------------------------------------------
// passA: qubits 0..9. Local 10-bit index == global bits 0-9, blk -> bits 10-17.
// mapping1: l = k | lane<<1 | w<<6           (k: bit0; lane: 1-5; w: 6-9)
// mapping2: l = k<<6 | (lane&7)<<7 | ((lane>>3)&1) | ((lane>>4)&1)<<1 | w<<2
// ---------------------------------------------------------------------------
__global__ void __launch_bounds__(512) qk_passA(int layer, int init) {
    __shared__ float2 sm[1024];
    __shared__ float4 sMat[20];
    int tid = threadIdx.x;
    int lane = tid & 31;
    int w = tid >> 5;                               // 0..15
    int blk = blockIdx.x;
    int s = blk >> 8;
    unsigned blkbase = ((unsigned)(blk & 255)) << 10;
    float2* psi = d_psi[s];

    if (tid < 20) sMat[tid] = (&d_mats[s][layer][0][0])[tid];

    unsigned l1 = ((unsigned)lane << 1) | ((unsigned)w << 6);
    float2 v[2];

    if (init) {
        v[0] = make_float2(0.f, 0.f);
        v[1] = make_float2(0.f, 0.f);
        if ((blkbase | l1) == 0) v[0] = make_float2(1.f, 0.f);
    } else {
        float4 a = *(const float4*)(psi + blkbase + l1);
        v[0] = make_float2(a.x, a.y);
        v[1] = make_float2(a.z, a.w);
    }
    __syncthreads();                                // sMat ready

    // q0: reg gate
    gate_pair(v[0], v[1], sMat[0], sMat[1]);
    // q1..q5: shfl (lane bits 0-4 <-> local bits 1-5)
    SHFL_GATE(1, 1)
    SHFL_GATE(2, 2)
    SHFL_GATE(3, 4)
    SHFL_GATE(4, 8)
    SHFL_GATE(5, 16)

    // transpose
    sm[swz(l1)] = v[0];
    sm[swz(l1 | 1u)] = v[1];
    __syncthreads();

    unsigned base2 = (((unsigned)lane & 7u) << 7) | (((unsigned)lane >> 3) & 1u)
                   | ((((unsigned)lane >> 4) & 1u) << 1) | ((unsigned)w << 2);
    v[0] = sm[swz(base2)];
    v[1] = sm[swz(base2 | 64u)];

    // q6: reg gate
    gate_pair(v[0], v[1], sMat[12], sMat[13]);
    // q7,q8,q9: shfl (lane bits 0-2 <-> local bits 7,8,9)
    SHFL_GATE(7, 1)
    SHFL_GATE(8, 2)
    SHFL_GATE(9, 4)

    psi[blkbase + base2] = v[0];
    psi[blkbase + base2 + 64u] = v[1];
}

// ---------------------------------------------------------------------------
// passB: qubits 10..17 + CZ sign. Block owns global bits {0,1,10..17};
// global(l) = (l&3) | rest<<2 | (l>>2)<<10, rest = blk bits -> global 2-9.
// mapping1: local bits 2-5 (= global 10-13) on lane bits 1-4.
// mapping2: local 6 (g14) reg; local 7,8,9 (g15,16,17) on lane bits 0-2.
// ---------------------------------------------------------------------------
__global__ void __launch_bounds__(512) qk_passB(int layer) {
    __shared__ float2 sm[1024];
    __shared__ float4 sMat[16];
    int tid = threadIdx.x;
    int lane = tid & 31;
    int w = tid >> 5;
    int blk = blockIdx.x;
    int s = blk >> 8;
    unsigned rest = (unsigned)(blk & 255);
    float2* psi = d_psi[s];

    if (tid < 16) sMat[tid] = (&d_mats[s][layer][10][0])[tid];

    unsigned l1 = ((unsigned)lane << 1) | ((unsigned)w << 6);
    unsigned g1 = (l1 & 3u) | (rest << 2) | ((l1 >> 2) << 10);

    float4 a = *(const float4*)(psi + g1);
    float2 v[2];
    v[0] = make_float2(a.x, a.y);
    v[1] = make_float2(a.z, a.w);
    __syncthreads();                                // sMat ready

    // q10..q13: shfl (lane bits 1-4 <-> local bits 2-5)
    SHFL_GATE(0, 2)
    SHFL_GATE(1, 4)
    SHFL_GATE(2, 8)
    SHFL_GATE(3, 16)

    sm[swz(l1)] = v[0];
    sm[swz(l1 | 1u)] = v[1];
    __syncthreads();

    unsigned base2 = (((unsigned)lane & 7u) << 7) | (((unsigned)lane >> 3) & 1u)
                   | ((((unsigned)lane >> 4) & 1u) << 1) | ((unsigned)w << 2);
    v[0] = sm[swz(base2)];
    v[1] = sm[swz(base2 | 64u)];

    // q14: reg gate (local bit 6)
    gate_pair(v[0], v[1], sMat[8], sMat[9]);
    // q15,16,17: shfl (lane bits 0-2 <-> local bits 7,8,9)
    SHFL_GATE(5, 1)
    SHFL_GATE(6, 2)
    SHFL_GATE(7, 4)

    // CZ chain sign + store
#pragma unroll
    for (int k = 0; k < 2; k++) {
        unsigned l2 = base2 | ((unsigned)k << 6);
        unsigned g = (l2 & 3u) | (rest << 2) | ((l2 >> 2) << 10);
        unsigned tm = g & (g >> 1) & 0x1FFFFu;
        if (__popc(tm) & 1) {
            v[k].x = -v[k].x;
            v[k].y = -v[k].y;
        }
        psi[g] = v[k];
    }
}

__global__ void qk_reduce() {
    int t = blockIdx.x * blockDim.x + threadIdx.x;
    int nthreads = gridDim.x * blockDim.x;
    double re = 0.0, im = 0.0;
    for (int i = t; i < NSTATE; i += nthreads) {
        float2 a = d_psi[0][i];
        float2 b = d_psi[1][i];
        re += (double)b.x * a.x + (double)b.y * a.y;
        im += (double)b.x * a.y - (double)b.y * a.x;
    }
#pragma unroll
    for (int o = 16; o > 0; o >>= 1) {
        re += __shfl_down_sync(0xFFFFFFFFu, re, o);
        im += __shfl_down_sync(0xFFFFFFFFu, im, o);
    }
    if ((threadIdx.x & 31) == 0) {
        atomicAdd(&d_acc[0], re);
        atomicAdd(&d_acc[1], im);
    }
}

__global__ void qk_final(float* out) {
    double re = d_acc[0], im = d_acc[1];
    out[0] = (float)(re * re + im * im);
}

extern "C" void kernel_launch(void* const* d_in, const int* in_sizes, int n_in,
                              void* d_out, int out_size) {
    const float* x1 = (const float*)d_in[0];
    const float* x2 = (const float*)d_in[1];
    const float* iscale = (const float*)d_in[2];
    const float* var = (const float*)d_in[3];

    qk_prep<<<1, 256>>>(x1, x2, iscale, var);
    for (int l = 0; l < NL; l++) {
        qk_passA<<<512, 512>>>(l, l == 0 ? 1 : 0);
        qk_passB<<<512, 512>>>(l);
    }
    qk_reduce<<<148, 256>>>();
    qk_final<<<1, 1>>>((float*)d_out);
}

// round 7
// speedup vs baseline: 1.5329x; 1.2064x over previous
#include <cuda_runtime.h>
#include <cuda_bf16.h>

// ---------------------------------------------------------------------------
// 18-qubit statevector fidelity |<psi2|psi1>|^2, hardware-efficient ansatz.
// R7: R5 structure (4 amps/thread, 512x256) with coalescing-fixed mapping 2:
// lane' covers amp bits {0,1,2,3,9} so mapping-2 global stores are 128B/32B
// contiguous runs instead of 8B scatter. Swizzle swz(l)=l^((l>>4)&3) is
// conflict-free for both smem transpose phases.
//   passA: q0,q1(reg k) q2-6(shfl) | transpose | q7,q8(reg k') q9(shfl)
//   passB: q10-14(shfl)           | transpose | q15,16(reg k') q17(shfl)+CZ
// ---------------------------------------------------------------------------

#define NQ 18
#define NL 6
#define NSTATE (1 << NQ)

__device__ float2 d_psi[2][NSTATE];
// per (s,l,q): f4[0]=(m00.x,m00.y,m01.x,m01.y), f4[1]=(m10.x,m10.y,m11.x,m11.y)
__device__ float4 d_mats[2][NL][NQ][2];
__device__ double d_acc[2];

__device__ __forceinline__ float2 cmulh(float2 a, float2 b) {
    return make_float2(a.x * b.x - a.y * b.y, a.x * b.y + a.y * b.x);
}
__device__ __forceinline__ float2 caddh(float2 a, float2 b) {
    return make_float2(a.x + b.x, a.y + b.y);
}
__device__ __forceinline__ float2 rscaleh(float r, float2 v) {
    return make_float2(r * v.x, r * v.y);
}

__global__ void qk_prep(const float* __restrict__ x1, const float* __restrict__ x2,
                        const float* __restrict__ iscale, const float* __restrict__ var) {
    int t = threadIdx.x;
    if (t < 2) d_acc[t] = 0.0;
    if (t >= 2 * NL * NQ) return;
    int s = t / (NL * NQ);
    int r = t % (NL * NQ);
    int l = r / NQ;
    int q = r % NQ;
    const float* x = s ? x2 : x1;

    float a = iscale[l * NQ + q] * x[q];
    float b = var[l * 2 * NQ + q];
    float c = var[l * 2 * NQ + NQ + q];

    float sa, ca, sb, cb, sc, cc;
    sincosf(0.5f * a, &sa, &ca);
    sincosf(0.5f * b, &sb, &cb);
    sincosf(0.5f * c, &sc, &cc);

    float2 X00 = make_float2(ca, 0.f), X01 = make_float2(0.f, -sa);
    float2 X10 = make_float2(0.f, -sa), X11 = make_float2(ca, 0.f);
    float2 M100 = caddh(rscaleh(cb, X00), rscaleh(-sb, X10));
    float2 M101 = caddh(rscaleh(cb, X01), rscaleh(-sb, X11));
    float2 M110 = caddh(rscaleh(sb, X00), rscaleh(cb, X10));
    float2 M111 = caddh(rscaleh(sb, X01), rscaleh(cb, X11));
    float2 e0 = make_float2(cc, -sc);
    float2 e1 = make_float2(cc, sc);
    float2 m00 = cmulh(e0, M100);
    float2 m01 = cmulh(e0, M101);
    float2 m10 = cmulh(e1, M110);
    float2 m11 = cmulh(e1, M111);

    d_mats[s][l][q][0] = make_float4(m00.x, m00.y, m01.x, m01.y);
    d_mats[s][l][q][1] = make_float4(m10.x, m10.y, m11.x, m11.y);
}

__device__ __forceinline__ void gate_pair(float2& a, float2& b, float4 c0, float4 c1) {
    float nax = fmaf(c0.z, b.x, fmaf(-c0.w, b.y, fmaf(c0.x, a.x, -c0.y * a.y)));
    float nay = fmaf(c0.z, b.y, fmaf(c0.w, b.x, fmaf(c0.x, a.y, c0.y * a.x)));
    float nbx = fmaf(c1.z, b.x, fmaf(-c1.w, b.y, fmaf(c1.x, a.x, -c1.y * a.y)));
    float nby = fmaf(c1.z, b.y, fmaf(c1.w, b.x, fmaf(c1.x, a.y, c1.y * a.x)));
    a = make_float2(nax, nay);
    b = make_float2(nbx, nby);
}

__device__ __forceinline__ float2 gate_shfl(float2 v, int mask,
                                            float cax, float cay, float cbx, float cby) {
    float px = __shfl_xor_sync(0xFFFFFFFFu, v.x, mask);
    float py = __shfl_xor_sync(0xFFFFFFFFu, v.y, mask);
    float rx = fmaf(cbx, px, fmaf(-cby, py, fmaf(cax, v.x, -cay * v.y)));
    float ry = fmaf(cbx, py, fmaf(cby, px, fmaf(cax, v.y, cay * v.x)));
    return make_float2(rx, ry);
}

// smem swizzle: fold amp bits 4,5 into bits 0,1.
// STS phase (lanes vary bits 2-6): slot mod 16 = (lane&3)<<2 | ((lane>>2)&3) distinct.
// LDS phase (lanes vary bits 0-3,9): slot = (lane&15) ^ const distinct.
__device__ __forceinline__ unsigned swz(unsigned l) {
    return l ^ ((l >> 4) & 3u);
}

#define SHFL_GATE(j, mask)                                                    \
    {                                                                         \
        float4 c0 = sMat[2 * (j)], c1 = sMat[2 * (j) + 1];                    \
        bool hi = (lane & (mask)) != 0;                                       \
        float cax = hi ? c1.z : c0.x;                                         \
        float cay = hi ? c1.w : c0.y;                                         \
        float cbx = hi ? c1.x : c0.z;                                         \
        float cby = hi ? c1.y : c0.w;                                         \
        _Pragma("unroll") for (int k = 0; k < 4; k++)                         \
            v[k] = gate_shfl(v[k], (mask), cax, cay, cbx, cby);               \
    }

// ---------------------------------------------------------------------------
// passA: qubits 0..9. Local 10-bit index == global bits 0-9; blk -> bits 10-17.
// mapping1: l = k | lane<<2 | w<<7          (k: bits 0,1; lane: 2-6; w: 7-9)
// mapping2: l = (lane&15) | ((lane>>4)<<9) | w<<4 | k<<7
//           (lane': bits 0-3 and 9; w': 4-6; k': 7,8)
// ---------------------------------------------------------------------------
__global__ void __launch_bounds__(256) qk_passA(int layer, int init) {
    __shared__ float2 sm[1024];
    __shared__ float4 sMat[20];
    int tid = threadIdx.x;
    int lane = tid & 31;
    int w = tid >> 5;                               // 0..7
    int blk = blockIdx.x;
    int s = blk >> 8;
    unsigned blkbase = ((unsigned)(blk & 255)) << 10;
    float2* psi = d_psi[s];

    if (tid < 20) sMat[tid] = (&d_mats[s][layer][0][0])[tid];

    unsigned l1 = ((unsigned)lane << 2) | ((unsigned)w << 7);
    float2 v[4];

    if (init) {
#pragma unroll
        for (int k = 0; k < 4; k++) v[k] = make_float2(0.f, 0.f);
        if ((blkbase | l1) == 0) v[0] = make_float2(1.f, 0.f);
    } else {
        const float4* p4 = (const float4*)(psi + blkbase + l1);
        float4 a = p4[0], b = p4[1];
        v[0] = make_float2(a.x, a.y);
        v[1] = make_float2(a.z, a.w);
        v[2] = make_float2(b.x, b.y);
        v[3] = make_float2(b.z, b.w);
    }
    __syncthreads();                                // sMat ready

    // q0 (k stride 1), q1 (k stride 2)
    {
        float4 c0 = sMat[0], c1 = sMat[1];
        gate_pair(v[0], v[1], c0, c1);
        gate_pair(v[2], v[3], c0, c1);
    }
    {
        float4 c0 = sMat[2], c1 = sMat[3];
        gate_pair(v[0], v[2], c0, c1);
        gate_pair(v[1], v[3], c0, c1);
    }
    // q2..q6: shfl (lane bits 0-4)
    SHFL_GATE(2, 1)
    SHFL_GATE(3, 2)
    SHFL_GATE(4, 4)
    SHFL_GATE(5, 8)
    SHFL_GATE(6, 16)

    // transpose (k bits 0,1 fold into swizzled low bits via XOR)
    unsigned sb1 = swz(l1);
#pragma unroll
    for (int k = 0; k < 4; k++) sm[sb1 ^ (unsigned)k] = v[k];
    __syncthreads();

    unsigned base2 = ((unsigned)lane & 15u) | (((unsigned)lane >> 4) << 9)
                   | ((unsigned)w << 4);
    unsigned sb2 = swz(base2);
#pragma unroll
    for (int k = 0; k < 4; k++) v[k] = sm[sb2 + ((unsigned)k << 7)];

    // q7 (k' stride 1), q8 (k' stride 2)
    {
        float4 c0 = sMat[14], c1 = sMat[15];
        gate_pair(v[0], v[1], c0, c1);
        gate_pair(v[2], v[3], c0, c1);
    }
    {
        float4 c0 = sMat[16], c1 = sMat[17];
        gate_pair(v[0], v[2], c0, c1);
        gate_pair(v[1], v[3], c0, c1);
    }
    // q9: shfl (lane' bit 4)
    SHFL_GATE(9, 16)

    // stores: 16 lanes cover 128B contiguous per k'
#pragma unroll
    for (int k = 0; k < 4; k++)
        psi[blkbase + base2 + ((unsigned)k << 7)] = v[k];
}

// ---------------------------------------------------------------------------
// passB: qubits 10..17 + CZ sign. Local l: bits 0,1 -> global 0,1;
// bits 2-9 -> global 10-17; rest (blk) -> global 2-9.
// g(l) = (l&3) | rest<<2 | (l>>2)<<10
// mapping1: k = bits 0,1; lane: 2-6 (g10-14 shfl); w: 7-9
// mapping2: lane' = {0,1,2,3,9}; w' = {4,5,6}; k' = {7,8} (g15,16 reg; g17 shfl)
// ---------------------------------------------------------------------------
__global__ void __launch_bounds__(256) qk_passB(int layer) {
    __shared__ float2 sm[1024];
    __shared__ float4 sMat[16];
    int tid = threadIdx.x;
    int lane = tid & 31;
    int w = tid >> 5;
    int blk = blockIdx.x;
    int s = blk >> 8;
    unsigned rest = (unsigned)(blk & 255);
    float2* psi = d_psi[s];

    if (tid < 16) sMat[tid] = (&d_mats[s][layer][10][0])[tid];

    unsigned l1 = ((unsigned)lane << 2) | ((unsigned)w << 7);
    unsigned g1 = (l1 & 3u) | (rest << 2) | ((l1 >> 2) << 10);

    float2 v[4];
    {
        const float4* p4 = (const float4*)(psi + g1);
        float4 a = p4[0], b = p4[1];
        v[0] = make_float2(a.x, a.y);
        v[1] = make_float2(a.z, a.w);
        v[2] = make_float2(b.x, b.y);
        v[3] = make_float2(b.z, b.w);
    }
    __syncthreads();                                // sMat ready

    // q10..q14: shfl (lane bits 0-4); j = q-10
    SHFL_GATE(0, 1)
    SHFL_GATE(1, 2)
    SHFL_GATE(2, 4)
    SHFL_GATE(3, 8)
    SHFL_GATE(4, 16)

    unsigned sb1 = swz(l1);
#pragma unroll
    for (int k = 0; k < 4; k++) sm[sb1 ^ (unsigned)k] = v[k];
    __syncthreads();

    unsigned base2 = ((unsigned)lane & 15u) | (((unsigned)lane >> 4) << 9)
                   | ((unsigned)w << 4);
    unsigned sb2 = swz(base2);
#pragma unroll
    for (int k = 0; k < 4; k++) v[k] = sm[sb2 + ((unsigned)k << 7)];

    // q15 (k' stride 1), q16 (k' stride 2)
    {
        float4 c0 = sMat[10], c1 = sMat[11];
        gate_pair(v[0], v[1], c0, c1);
        gate_pair(v[2], v[3], c0, c1);
    }
    {
        float4 c0 = sMat[12], c1 = sMat[13];
        gate_pair(v[0], v[2], c0, c1);
        gate_pair(v[1], v[3], c0, c1);
    }
    // q17: shfl (lane' bit 4); j = 7
    SHFL_GATE(7, 16)

    // CZ chain sign + store (32B-sector aligned groups)
#pragma unroll
    for (int k = 0; k < 4; k++) {
        unsigned l2 = base2 | ((unsigned)k << 7);
        unsigned g = (l2 & 3u) | (rest << 2) | ((l2 >> 2) << 10);
        unsigned tm = g & (g >> 1) & 0x1FFFFu;
        if (__popc(tm) & 1) {
            v[k].x = -v[k].x;
            v[k].y = -v[k].y;
        }
        psi[g] = v[k];
    }
}

__global__ void qk_reduce() {
    int t = blockIdx.x * blockDim.x + threadIdx.x;
    int nthreads = gridDim.x * blockDim.x;
    double re = 0.0, im = 0.0;
    for (int i = t; i < NSTATE; i += nthreads) {
        float2 a = d_psi[0][i];
        float2 b = d_psi[1][i];
        re += (double)b.x * a.x + (double)b.y * a.y;
        im += (double)b.x * a.y - (double)b.y * a.x;
    }
#pragma unroll
    for (int o = 16; o > 0; o >>= 1) {
        re += __shfl_down_sync(0xFFFFFFFFu, re, o);
        im += __shfl_down_sync(0xFFFFFFFFu, im, o);
    }
    if ((threadIdx.x & 31) == 0) {
        atomicAdd(&d_acc[0], re);
        atomicAdd(&d_acc[1], im);
    }
}

__global__ void qk_final(float* out) {
    double re = d_acc[0], im = d_acc[1];
    out[0] = (float)(re * re + im * im);
}

extern "C" void kernel_launch(void* const* d_in, const int* in_sizes, int n_in,
                              void* d_out, int out_size) {
    const float* x1 = (const float*)d_in[0];
    const float* x2 = (const float*)d_in[1];
    const float* iscale = (const float*)d_in[2];
    const float* var = (const float*)d_in[3];

    qk_prep<<<1, 256>>>(x1, x2, iscale, var);
    for (int l = 0; l < NL; l++) {
        qk_passA<<<512, 256>>>(l, l == 0 ? 1 : 0);
        qk_passB<<<512, 256>>>(l);
    }
    qk_reduce<<<148, 256>>>();
    qk_final<<<1, 1>>>((float*)d_out);
}